// round 1
// baseline (speedup 1.0000x reference)
#include <cuda_runtime.h>
#include <math.h>

#define D      128
#define TWO_D  256
#define MTILE  64
#define NTHREADS 256
#define KC     32

// Scratch for scatter-accumulated neighbor features: [2, 50000, 128] fp32 = 51.2MB
__device__ float g_neighbor[2 * 50000 * 128];

// ---------------------------------------------------------------------------
// Kernel 1: zero the neighbor accumulator
// ---------------------------------------------------------------------------
__global__ void zero_kernel(int n4) {
    int i = blockIdx.x * blockDim.x + threadIdx.x;
    if (i < n4) reinterpret_cast<float4*>(g_neighbor)[i] = make_float4(0.f, 0.f, 0.f, 0.f);
}

// ---------------------------------------------------------------------------
// Kernel 2: edge scatter-add. One warp per edge; lane owns one float4 (32x4=128).
// Vector RED (red.global.add.v4.f32) -> 16B per atomic op, L2-resident.
// ---------------------------------------------------------------------------
__global__ void scatter_kernel(const float* __restrict__ x,
                               const int* __restrict__ esrc,
                               const int* __restrict__ edst,
                               int E, int N) {
    int e    = (blockIdx.x * blockDim.x + threadIdx.x) >> 5;
    int lane = threadIdx.x & 31;
    if (e >= E) return;
    int s = esrc[e];
    int t = edst[e];
#pragma unroll
    for (int b = 0; b < 2; b++) {
        const float4 v = *reinterpret_cast<const float4*>(
            x + ((size_t)(b * N + s)) * D + lane * 4);
        float* p = g_neighbor + ((size_t)(b * N + t)) * D + lane * 4;
        asm volatile("red.global.add.v4.f32 [%0], {%1, %2, %3, %4};"
                     :: "l"(p), "f"(v.x), "f"(v.y), "f"(v.z), "f"(v.w)
                     : "memory");
    }
}

// ---------------------------------------------------------------------------
// Kernel 3: fused LayerNorm(x) ++ LayerNorm(neighbor/deg) -> GEMM1(256x256)
//           -> bias+GELU(exact erf) -> GEMM2(256x128) -> bias + residual.
// Block = 64 rows. Activations live transposed [k][m] in smem with an XOR
// swizzle on m (granularity 4 words) so GEMM a-fetches are two LDS.128 and
// the LN transposed scalar stores are only ~4-way conflicted.
// ---------------------------------------------------------------------------
__device__ __forceinline__ int swz(int k) { return ((k >> 2) & 15) << 2; }

__global__ __launch_bounds__(NTHREADS, 2)
void fused_kernel(const float* __restrict__ x, const float* __restrict__ degree,
                  const float* __restrict__ sn_g, const float* __restrict__ sn_b,
                  const float* __restrict__ nn_g, const float* __restrict__ nn_b,
                  const float* __restrict__ W1, const float* __restrict__ b1,
                  const float* __restrict__ W2, const float* __restrict__ b2,
                  float* __restrict__ out, int N, int nrows) {
    extern __shared__ float sm[];
    float* sA = sm;                     // [256][64] swizzled (h0^T, later h1^T)
    float* wt = sm + TWO_D * MTILE;     // [32][256] weight chunk staging

    const int tid  = threadIdx.x;
    const int lane = tid & 31;
    const int warp = tid >> 5;
    const int row0 = blockIdx.x * MTILE;

    // ---------------- Stage 1: LayerNorms, write transposed into sA ----------
    {
        const float4 g1  = *reinterpret_cast<const float4*>(sn_g + lane * 4);
        const float4 be1 = *reinterpret_cast<const float4*>(sn_b + lane * 4);
        const float4 g2  = *reinterpret_cast<const float4*>(nn_g + lane * 4);
        const float4 be2 = *reinterpret_cast<const float4*>(nn_b + lane * 4);
#pragma unroll
        for (int rr = 0; rr < 8; rr++) {
            const int r    = warp * 8 + rr;   // 0..63
            const int grow = row0 + r;
            const int k0   = lane * 4;
            const int s0   = swz(k0);         // same for all 4 cols (k0 % 4 == 0)
            const int s1   = swz(k0 + 128);
            if (grow < nrows) {
                // ---- LN(x) ----
                float4 xv = *reinterpret_cast<const float4*>(x + (size_t)grow * D + lane * 4);
                float sum  = xv.x + xv.y + xv.z + xv.w;
                float sumq = xv.x * xv.x + xv.y * xv.y + xv.z * xv.z + xv.w * xv.w;
#pragma unroll
                for (int o = 16; o > 0; o >>= 1) {
                    sum  += __shfl_xor_sync(0xffffffffu, sum, o);
                    sumq += __shfl_xor_sync(0xffffffffu, sumq, o);
                }
                float m    = sum * (1.0f / 128.0f);
                float rstd = rsqrtf(sumq * (1.0f / 128.0f) - m * m + 1e-5f);
                sA[(k0 + 0) * MTILE + (r ^ s0)] = (xv.x - m) * rstd * g1.x + be1.x;
                sA[(k0 + 1) * MTILE + (r ^ s0)] = (xv.y - m) * rstd * g1.y + be1.y;
                sA[(k0 + 2) * MTILE + (r ^ s0)] = (xv.z - m) * rstd * g1.z + be1.z;
                sA[(k0 + 3) * MTILE + (r ^ s0)] = (xv.w - m) * rstd * g1.w + be1.w;
                // ---- LN(neighbor / clip(degree,1)) ----
                int   node = grow % N;
                float inv  = 1.0f / fmaxf(degree[node], 1.0f);
                float4 nv = *reinterpret_cast<const float4*>(
                    g_neighbor + (size_t)grow * D + lane * 4);
                nv.x *= inv; nv.y *= inv; nv.z *= inv; nv.w *= inv;
                sum  = nv.x + nv.y + nv.z + nv.w;
                sumq = nv.x * nv.x + nv.y * nv.y + nv.z * nv.z + nv.w * nv.w;
#pragma unroll
                for (int o = 16; o > 0; o >>= 1) {
                    sum  += __shfl_xor_sync(0xffffffffu, sum, o);
                    sumq += __shfl_xor_sync(0xffffffffu, sumq, o);
                }
                m    = sum * (1.0f / 128.0f);
                rstd = rsqrtf(sumq * (1.0f / 128.0f) - m * m + 1e-5f);
                sA[(k0 + 128) * MTILE + (r ^ s1)] = (nv.x - m) * rstd * g2.x + be2.x;
                sA[(k0 + 129) * MTILE + (r ^ s1)] = (nv.y - m) * rstd * g2.y + be2.y;
                sA[(k0 + 130) * MTILE + (r ^ s1)] = (nv.z - m) * rstd * g2.z + be2.z;
                sA[(k0 + 131) * MTILE + (r ^ s1)] = (nv.w - m) * rstd * g2.w + be2.w;
            } else {
#pragma unroll
                for (int j = 0; j < 4; j++) {
                    sA[(k0 + j)       * MTILE + (r ^ s0)] = 0.f;
                    sA[(k0 + 128 + j) * MTILE + (r ^ s1)] = 0.f;
                }
            }
        }
    }
    __syncthreads();

    // ---------------- Stage 2: GEMM1 (64x256x256), 8x8 register tiles --------
    const int tm = tid & 7;     // m group: rows tm*8 .. tm*8+7
    const int tn = tid >> 3;    // n group: cols tn*8 .. tn*8+7  (0..31 -> 256)
    float c[8][8];
#pragma unroll
    for (int i = 0; i < 8; i++)
#pragma unroll
        for (int j = 0; j < 8; j++) c[i][j] = 0.f;

    for (int kc = 0; kc < TWO_D; kc += KC) {
        __syncthreads();
        // stage W1[kc..kc+31][0..255] -> wt
#pragma unroll
        for (int it = 0; it < (KC * TWO_D / 4) / NTHREADS; it++) {  // 8
            int idx = it * NTHREADS + tid;       // float4 index
            int kr  = idx >> 6;                  // row (64 float4/row)
            int nc  = (idx & 63) << 2;
            *reinterpret_cast<float4*>(wt + kr * TWO_D + nc) =
                *reinterpret_cast<const float4*>(W1 + (size_t)(kc + kr) * TWO_D + nc);
        }
        __syncthreads();
#pragma unroll 4
        for (int kk = 0; kk < KC; kk++) {
            const int k = kc + kk;
            const int s = swz(k);
            float4 a0  = *reinterpret_cast<const float4*>(sA + k * MTILE + ((tm * 8)     ^ s));
            float4 a1  = *reinterpret_cast<const float4*>(sA + k * MTILE + ((tm * 8 + 4) ^ s));
            float4 b0  = *reinterpret_cast<const float4*>(wt + kk * TWO_D + tn * 8);
            float4 b1v = *reinterpret_cast<const float4*>(wt + kk * TWO_D + tn * 8 + 4);
            float av[8] = {a0.x, a0.y, a0.z, a0.w, a1.x, a1.y, a1.z, a1.w};
            float bv[8] = {b0.x, b0.y, b0.z, b0.w, b1v.x, b1v.y, b1v.z, b1v.w};
#pragma unroll
            for (int i = 0; i < 8; i++)
#pragma unroll
                for (int j = 0; j < 8; j++) c[i][j] += av[i] * bv[j];
        }
    }
    __syncthreads();

    // ---------------- Stage 3: bias + exact GELU, write h1^T back into sA ----
    {
        float4 bb0 = *reinterpret_cast<const float4*>(b1 + tn * 8);
        float4 bb1 = *reinterpret_cast<const float4*>(b1 + tn * 8 + 4);
        float bvv[8] = {bb0.x, bb0.y, bb0.z, bb0.w, bb1.x, bb1.y, bb1.z, bb1.w};
#pragma unroll
        for (int j = 0; j < 8; j++) {
            const int n = tn * 8 + j;
            const int s = swz(n);
#pragma unroll
            for (int i = 0; i < 8; i++) {
                float v = c[i][j] + bvv[j];
                v = 0.5f * v * (1.0f + erff(v * 0.70710678118654752f));
                sA[n * MTILE + ((tm * 8 + i) ^ s)] = v;
            }
        }
    }
    __syncthreads();

    // ---------------- Stage 4: GEMM2 (64x128x256), 8x4 register tiles --------
    const int tn2 = tid >> 3;   // 0..31 -> cols tn2*4 .. tn2*4+3 (128)
    float c2[8][4];
#pragma unroll
    for (int i = 0; i < 8; i++)
#pragma unroll
        for (int j = 0; j < 4; j++) c2[i][j] = 0.f;

    for (int kc = 0; kc < TWO_D; kc += KC) {
        __syncthreads();
        // stage W2[kc..kc+31][0..127] -> wt
#pragma unroll
        for (int it = 0; it < (KC * D / 4) / NTHREADS; it++) {      // 4
            int idx = it * NTHREADS + tid;
            int kr  = idx >> 5;                  // 32 float4/row
            int nc  = (idx & 31) << 2;
            *reinterpret_cast<float4*>(wt + kr * D + nc) =
                *reinterpret_cast<const float4*>(W2 + (size_t)(kc + kr) * D + nc);
        }
        __syncthreads();
#pragma unroll 4
        for (int kk = 0; kk < KC; kk++) {
            const int k = kc + kk;
            const int s = swz(k);
            float4 a0 = *reinterpret_cast<const float4*>(sA + k * MTILE + ((tm * 8)     ^ s));
            float4 a1 = *reinterpret_cast<const float4*>(sA + k * MTILE + ((tm * 8 + 4) ^ s));
            float4 b0 = *reinterpret_cast<const float4*>(wt + kk * D + tn2 * 4);
            float av[8] = {a0.x, a0.y, a0.z, a0.w, a1.x, a1.y, a1.z, a1.w};
#pragma unroll
            for (int i = 0; i < 8; i++) {
                c2[i][0] += av[i] * b0.x;
                c2[i][1] += av[i] * b0.y;
                c2[i][2] += av[i] * b0.z;
                c2[i][3] += av[i] * b0.w;
            }
        }
    }

    // ---------------- Stage 5: bias + residual + store ----------------------
    {
        float4 bb = *reinterpret_cast<const float4*>(b2 + tn2 * 4);
#pragma unroll
        for (int i = 0; i < 8; i++) {
            int grow = row0 + tm * 8 + i;
            if (grow < nrows) {
                float4 xv = *reinterpret_cast<const float4*>(x + (size_t)grow * D + tn2 * 4);
                float4 o;
                o.x = xv.x + c2[i][0] + bb.x;
                o.y = xv.y + c2[i][1] + bb.y;
                o.z = xv.z + c2[i][2] + bb.z;
                o.w = xv.w + c2[i][3] + bb.w;
                *reinterpret_cast<float4*>(out + (size_t)grow * D + tn2 * 4) = o;
            }
        }
    }
}

// ---------------------------------------------------------------------------
extern "C" void kernel_launch(void* const* d_in, const int* in_sizes, int n_in,
                              void* d_out, int out_size) {
    const float* x      = (const float*)d_in[0];
    const int*   esrc   = (const int*)  d_in[1];
    const int*   edst   = (const int*)  d_in[2];
    const float* degree = (const float*)d_in[3];
    const float* sn_g   = (const float*)d_in[4];
    const float* sn_b   = (const float*)d_in[5];
    const float* nn_g   = (const float*)d_in[6];
    const float* nn_b   = (const float*)d_in[7];
    const float* W1     = (const float*)d_in[8];
    const float* b1     = (const float*)d_in[9];
    const float* W2     = (const float*)d_in[10];
    const float* b2     = (const float*)d_in[11];

    const int E     = in_sizes[1];
    const int nrows = in_sizes[0] / D;   // B*N
    const int N     = in_sizes[3];       // degree length

    const int n4 = nrows * (D / 4);
    zero_kernel<<<(n4 + 255) / 256, 256>>>(n4);
    scatter_kernel<<<(E + 7) / 8, 256>>>(x, esrc, edst, E, N);

    const int smem = (TWO_D * MTILE + KC * TWO_D) * (int)sizeof(float); // 98304
    cudaFuncSetAttribute(fused_kernel, cudaFuncAttributeMaxDynamicSharedMemorySize, smem);
    fused_kernel<<<(nrows + MTILE - 1) / MTILE, NTHREADS, smem>>>(
        x, degree, sn_g, sn_b, nn_g, nn_b, W1, b1, W2, b2,
        (float*)d_out, N, nrows);
}